// round 8
// baseline (speedup 1.0000x reference)
#include <cuda_runtime.h>
#include <math.h>
#include <stdint.h>

#define BB  32
#define NN  1024
#define FIN 6
#define F1  128
#define F2  512
#define F3  1024
#define CLS 40

#define TBM 128
#define TBN 128
#define TBK 16

// ---------------- scratch (static __device__ — no allocation allowed) ----------------
__device__ float g_A   [(size_t)BB * NN * NN];   // adjacency exp(-d2), 128 MB
__device__ float g_feat[(size_t)BB * NN * F3];
__device__ float g_mid [(size_t)BB * NN * F2];
__device__ float g_t1  [(size_t)BB * NN * F2];
__device__ float g_t2  [(size_t)BB * NN * F2];
__device__ float g_sq  [BB * NN];
__device__ float g_dis [BB * NN];
__device__ float g_pool[BB * F3];
__device__ float g_fc1 [BB * 512];
__device__ float g_fc2 [BB * 128];

// ---------------- tf32 helpers ----------------
__device__ __forceinline__ float tf32f(float x) {
    uint32_t r;
    asm("cvt.rna.tf32.f32 %0, %1;" : "=r"(r) : "f"(x));
    return __uint_as_float(r);
}
__device__ __forceinline__ void mma_tf32(float* c, const uint32_t* a, const uint32_t* b) {
    asm volatile(
        "mma.sync.aligned.m16n8k8.row.col.f32.tf32.tf32.f32 "
        "{%0,%1,%2,%3}, {%4,%5,%6,%7}, {%8,%9}, {%0,%1,%2,%3};"
        : "+f"(c[0]), "+f"(c[1]), "+f"(c[2]), "+f"(c[3])
        : "r"(a[0]), "r"(a[1]), "r"(a[2]), "r"(a[3]), "r"(b[0]), "r"(b[1]));
}

// ---------------- row squared-norms ----------------
__global__ void rowsq_kernel(const float* __restrict__ x, float* __restrict__ sq, int F) {
    int row  = blockIdx.x * (blockDim.x / 32) + (threadIdx.x >> 5);
    int lane = threadIdx.x & 31;
    if (row >= BB * NN) return;
    const float* p = x + (size_t)row * F;
    float s = 0.f;
    for (int f = lane; f < F; f += 32) { float v = p[f]; s += v * v; }
    #pragma unroll
    for (int o = 16; o; o >>= 1) s += __shfl_down_sync(0xffffffffu, s, o);
    if (lane == 0) sq[row] = s;
}

// ---------------- SIMT gram (F=6): A = exp(2<x_n,x_m> - sq_n - sq_m) ----------------
__global__ void gram_exp_kernel(const float* __restrict__ X, const float* __restrict__ sq,
                                float* __restrict__ Aout, int F) {
    int b = blockIdx.z;
    const float* Xb  = X    + (size_t)b * NN * F;
    float*       Ab  = Aout + (size_t)b * NN * NN;
    const float* sqb = sq   + b * NN;

    int row0 = blockIdx.y * 64, col0 = blockIdx.x * 64;
    __shared__ float As[16][65];
    __shared__ float Bs[16][65];
    int tid = threadIdx.y * 16 + threadIdx.x;

    float acc[4][4];
    #pragma unroll
    for (int i = 0; i < 4; i++)
        #pragma unroll
        for (int j = 0; j < 4; j++) acc[i][j] = 0.f;

    for (int k0 = 0; k0 < F; k0 += 16) {
        #pragma unroll
        for (int t = 0; t < 4; t++) {
            int e = tid + t * 256;
            int r = e >> 4, k = e & 15;
            int kk = k0 + k;
            As[k][r] = (kk < F) ? Xb[(size_t)(row0 + r) * F + kk] : 0.f;
        }
        #pragma unroll
        for (int t = 0; t < 4; t++) {
            int e = tid + t * 256;
            int c = e >> 4, k = e & 15;
            int kk = k0 + k;
            Bs[k][c] = (kk < F) ? Xb[(size_t)(col0 + c) * F + kk] : 0.f;
        }
        __syncthreads();
        #pragma unroll
        for (int k = 0; k < 16; k++) {
            float a[4], bv[4];
            #pragma unroll
            for (int i = 0; i < 4; i++) a[i]  = As[k][threadIdx.y * 4 + i];
            #pragma unroll
            for (int j = 0; j < 4; j++) bv[j] = Bs[k][threadIdx.x * 4 + j];
            #pragma unroll
            for (int i = 0; i < 4; i++)
                #pragma unroll
                for (int j = 0; j < 4; j++) acc[i][j] += a[i] * bv[j];
        }
        __syncthreads();
    }

    #pragma unroll
    for (int i = 0; i < 4; i++) {
        int r = row0 + threadIdx.y * 4 + i;
        float sr = sqb[r];
        #pragma unroll
        for (int j = 0; j < 4; j++) {
            int c = col0 + threadIdx.x * 4 + j;
            Ab[(size_t)r * NN + c] = expf(2.f * acc[i][j] - sr - sqb[c]);
        }
    }
}

// ---------------- dis[b,n] = 1/sqrt(sum_m A[b,n,m]) — float4 reads ----------------
__global__ void deg_kernel(const float* __restrict__ A, float* __restrict__ dis) {
    int row  = blockIdx.x * (blockDim.x / 32) + (threadIdx.x >> 5);
    int lane = threadIdx.x & 31;
    if (row >= BB * NN) return;
    const float4* p = (const float4*)(A + (size_t)row * NN);
    float s = 0.f;
    for (int m = lane; m < NN / 4; m += 32) {
        float4 v = p[m];
        s += v.x + v.y + v.z + v.w;
    }
    #pragma unroll
    for (int o = 16; o; o >>= 1) s += __shfl_down_sync(0xffffffffu, s, o);
    if (lane == 0) dis[row] = 1.f / sqrtf(s);
}

// ---------------- tf32 tensor-core GEMM, k-paired float2 smem + XOR swizzle ----------
// acc = A @ B'  where B' = (dvec ? diag(dvec) : I) @ B
// epilogue:
//   expmode: C = exp(2*acc - sq_r - sq_c)
//   else:    C = (rs ? rs[r] : 1)*alpha*acc + beta*Cin + beta2*Cin2 + bias, opt. relu
// A: [1024, K] rm.  B normal: [K, Nc] rm.  B trans: [Nc=1024, K] rm.  K % 16 == 0.
__global__ __launch_bounds__(256) void tgemm_kernel(
    const float* __restrict__ A, const float* __restrict__ B,
    const float* __restrict__ Cin, const float* __restrict__ Cin2,
    const float* __restrict__ bias,
    const float* __restrict__ sqv, const float* __restrict__ rs,
    const float* __restrict__ dvec,
    float* __restrict__ C,
    int Nc, int K,
    long long sA, long long sB, long long sCin, long long sCin2, long long sC,
    float alpha, float beta, float beta2, int relu, int expmode, int transB)
{
    int bz = blockIdx.z;
    A += (size_t)bz * sA;
    B += (size_t)bz * sB;
    C += (size_t)bz * sC;
    if (Cin)  Cin  += (size_t)bz * sCin;
    if (Cin2) Cin2 += (size_t)bz * sCin2;
    const float* sqb = sqv  ? (sqv  + (size_t)bz * NN) : nullptr;
    const float* rsb = rs   ? (rs   + (size_t)bz * NN) : nullptr;
    const float* dv  = dvec ? (dvec + (size_t)bz * NN) : nullptr;

    int row0 = blockIdx.y * TBM, col0 = blockIdx.x * TBN;

    // [stage][kk-octet][row][4 float2 slots]; pair = (k, k+4), slot = c ^ ((row>>2)&3)
    __shared__ float2 As[2][2][TBM][4];
    __shared__ float2 Bs[2][2][TBN][4];

    int tid  = threadIdx.x;
    int lane = tid & 31;
    int warp = tid >> 5;
    int wrow = (warp >> 1) * 32;
    int wcol = (warp & 1) * 64;
    int g = lane >> 2, t4 = lane & 3;

    // A / transB loader: one row, one k-octet
    int mA  = tid & 127;
    int kkA = tid >> 7;          // 0/1
    int swA = (mA >> 2) & 3;
    // normal-B loader: k-pair (c, c+4) in octet kkB, 4 consecutive cols
    int kbB = tid >> 5;          // 0..7
    int kkB = kbB >> 2;
    int cB  = kbB & 3;
    int n4  = (tid & 31) * 4;
    bool vecB = (col0 + TBN) <= Nc;   // full tile, Nc mult of 4 cases

    float acc[2][8][4];
    #pragma unroll
    for (int r = 0; r < 2; r++)
        #pragma unroll
        for (int j = 0; j < 8; j++)
            #pragma unroll
            for (int q = 0; q < 4; q++) acc[r][j][q] = 0.f;

    int nt = K / TBK;

    float4 pa0, pa1, pb0, pb1;
    auto ldg_tile = [&](int k0) {
        const float* ap = &A[(size_t)(row0 + mA) * K + k0 + kkA * 8];
        pa0 = *(const float4*)ap;
        pa1 = *(const float4*)(ap + 4);
        if (transB) {
            const float* bp = &B[(size_t)(col0 + mA) * K + k0 + kkA * 8];
            pb0 = *(const float4*)bp;
            pb1 = *(const float4*)(bp + 4);
        } else {
            int klo = k0 + kkB * 8 + cB;
            if (vecB) {
                pb0 = *(const float4*)&B[(size_t)klo * Nc + col0 + n4];
                pb1 = *(const float4*)&B[(size_t)(klo + 4) * Nc + col0 + n4];
            } else {
                float* l = &pb0.x; float* h = &pb1.x;
                #pragma unroll
                for (int i = 0; i < 4; i++) {
                    int cc = col0 + n4 + i;
                    l[i] = (cc < Nc) ? B[(size_t)klo * Nc + cc] : 0.f;
                    h[i] = (cc < Nc) ? B[(size_t)(klo + 4) * Nc + cc] : 0.f;
                }
            }
            if (dv) {
                float dlo = dv[klo], dhi = dv[klo + 4];
                pb0.x *= dlo; pb0.y *= dlo; pb0.z *= dlo; pb0.w *= dlo;
                pb1.x *= dhi; pb1.y *= dhi; pb1.z *= dhi; pb1.w *= dhi;
            }
        }
    };

    auto sts_tile = [&](int buf) {
        {
            const float* lo = &pa0.x; const float* hi = &pa1.x;
            float2* row = As[buf][kkA][mA];
            #pragma unroll
            for (int c = 0; c < 4; c++) {
                float2 f; f.x = tf32f(lo[c]); f.y = tf32f(hi[c]);
                row[c ^ swA] = f;
            }
        }
        if (transB) {
            const float* lo = &pb0.x; const float* hi = &pb1.x;
            float2* row = Bs[buf][kkA][mA];
            #pragma unroll
            for (int c = 0; c < 4; c++) {
                float2 f; f.x = tf32f(lo[c]); f.y = tf32f(hi[c]);
                row[c ^ swA] = f;
            }
        } else {
            const float* lo = &pb0.x; const float* hi = &pb1.x;
            #pragma unroll
            for (int i = 0; i < 4; i++) {
                int n = n4 + i;
                float2 f; f.x = tf32f(lo[i]); f.y = tf32f(hi[i]);
                Bs[buf][kkB][n][cB ^ ((n >> 2) & 3)] = f;
            }
        }
    };

    ldg_tile(0);
    sts_tile(0);
    __syncthreads();

    for (int t = 0; t < nt; t++) {
        int buf = t & 1;
        if (t + 1 < nt) ldg_tile((t + 1) * TBK);

        #pragma unroll
        for (int kk = 0; kk < 2; kk++) {
            uint32_t af[2][4];
            #pragma unroll
            for (int r = 0; r < 2; r++) {
                int m0 = wrow + r * 16 + g;
                int m1 = m0 + 8;
                float2 alo = As[buf][kk][m0][t4 ^ ((m0 >> 2) & 3)];
                float2 ahi = As[buf][kk][m1][t4 ^ ((m1 >> 2) & 3)];
                af[r][0] = __float_as_uint(alo.x);
                af[r][1] = __float_as_uint(ahi.x);
                af[r][2] = __float_as_uint(alo.y);
                af[r][3] = __float_as_uint(ahi.y);
            }
            #pragma unroll
            for (int j = 0; j < 8; j++) {
                int n = wcol + j * 8 + g;
                float2 bv = Bs[buf][kk][n][t4 ^ ((n >> 2) & 3)];
                uint32_t bf[2] = { __float_as_uint(bv.x), __float_as_uint(bv.y) };
                mma_tf32(acc[0][j], af[0], bf);
                mma_tf32(acc[1][j], af[1], bf);
            }
        }

        if (t + 1 < nt) sts_tile(buf ^ 1);
        __syncthreads();
    }

    // ---- epilogue ----
    #pragma unroll
    for (int r = 0; r < 2; r++) {
        int rr = row0 + wrow + r * 16 + g;
        float s0 = rsb ? rsb[rr] * alpha : alpha;
        float s1 = rsb ? rsb[rr + 8] * alpha : alpha;
        #pragma unroll
        for (int j = 0; j < 8; j++) {
            int cc = col0 + wcol + j * 8 + t4 * 2;
            float* v = acc[r][j];
            if (expmode) {
                float sr0 = sqb[rr], sr1 = sqb[rr + 8];
                float sc0 = sqb[cc], sc1 = sqb[cc + 1];
                C[(size_t)rr * Nc + cc]           = expf(2.f * v[0] - sr0 - sc0);
                C[(size_t)rr * Nc + cc + 1]       = expf(2.f * v[1] - sr0 - sc1);
                C[(size_t)(rr + 8) * Nc + cc]     = expf(2.f * v[2] - sr1 - sc0);
                C[(size_t)(rr + 8) * Nc + cc + 1] = expf(2.f * v[3] - sr1 - sc1);
            } else {
                #pragma unroll
                for (int h = 0; h < 2; h++) {
                    int rrr = rr + h * 8;
                    float sa = h ? s1 : s0;
                    #pragma unroll
                    for (int q = 0; q < 2; q++) {
                        int ccc = cc + q;
                        if (ccc >= Nc) continue;
                        float w = sa * v[h * 2 + q];
                        if (Cin)  w += beta  * Cin [(size_t)rrr * Nc + ccc];
                        if (Cin2) w += beta2 * Cin2[(size_t)rrr * Nc + ccc];
                        if (bias) w += bias[ccc];
                        if (relu) w = fmaxf(w, 0.f);
                        C[(size_t)rrr * Nc + ccc] = w;
                    }
                }
            }
        }
    }
}

// ---------------- SIMT fallback SGEMM (64x64) — small / K%16!=0 cases ----------------
__global__ void gemm_kernel(const float* __restrict__ A, const float* __restrict__ B,
                            const float* __restrict__ Cin, const float* __restrict__ bias,
                            float* __restrict__ C,
                            int M, int Nc, int K,
                            long long sA, long long sB, long long sCin, long long sC,
                            float alpha, float beta, int relu) {
    int bz = blockIdx.z;
    A += (size_t)bz * sA;
    B += (size_t)bz * sB;
    C += (size_t)bz * sC;
    if (Cin) Cin += (size_t)bz * sCin;

    int row0 = blockIdx.y * 64, col0 = blockIdx.x * 64;
    __shared__ float As[16][65];
    __shared__ float Bs[16][65];
    int tid = threadIdx.y * 16 + threadIdx.x;

    float acc[4][4];
    #pragma unroll
    for (int i = 0; i < 4; i++)
        #pragma unroll
        for (int j = 0; j < 4; j++) acc[i][j] = 0.f;

    for (int k0 = 0; k0 < K; k0 += 16) {
        #pragma unroll
        for (int t = 0; t < 4; t++) {
            int e = tid + t * 256;
            int r = e >> 4, k = e & 15;
            int kk = k0 + k, rr = row0 + r;
            As[k][r] = (kk < K && rr < M) ? A[(size_t)rr * K + kk] : 0.f;
        }
        #pragma unroll
        for (int t = 0; t < 4; t++) {
            int e = tid + t * 256;
            int k = e >> 6, c = e & 63;
            int kk = k0 + k, cc = col0 + c;
            Bs[k][c] = (kk < K && cc < Nc) ? B[(size_t)kk * Nc + cc] : 0.f;
        }
        __syncthreads();
        #pragma unroll
        for (int k = 0; k < 16; k++) {
            float a[4], bv[4];
            #pragma unroll
            for (int i = 0; i < 4; i++) a[i]  = As[k][threadIdx.y * 4 + i];
            #pragma unroll
            for (int j = 0; j < 4; j++) bv[j] = Bs[k][threadIdx.x * 4 + j];
            #pragma unroll
            for (int i = 0; i < 4; i++)
                #pragma unroll
                for (int j = 0; j < 4; j++) acc[i][j] += a[i] * bv[j];
        }
        __syncthreads();
    }

    #pragma unroll
    for (int i = 0; i < 4; i++) {
        int r = row0 + threadIdx.y * 4 + i;
        if (r >= M) continue;
        #pragma unroll
        for (int j = 0; j < 4; j++) {
            int c = col0 + threadIdx.x * 4 + j;
            if (c >= Nc) continue;
            float v = alpha * acc[i][j];
            if (Cin)  v += beta * Cin[(size_t)r * Nc + c];
            if (bias) v += bias[c];
            if (relu) v = fmaxf(v, 0.f);
            C[(size_t)r * Nc + c] = v;
        }
    }
}

// ---------------- global max pool over n (float4 over features) ----------------
__global__ void maxpool_kernel(const float4* __restrict__ X, float4* __restrict__ out) {
    int f4 = blockIdx.x * blockDim.x + threadIdx.x;
    int b = blockIdx.y;
    if (f4 >= F3 / 4) return;
    const float4* p = X + (size_t)b * NN * (F3 / 4) + f4;
    float4 m = make_float4(-INFINITY, -INFINITY, -INFINITY, -INFINITY);
    for (int n = 0; n < NN; n++) {
        float4 v = p[(size_t)n * (F3 / 4)];
        m.x = fmaxf(m.x, v.x); m.y = fmaxf(m.y, v.y);
        m.z = fmaxf(m.z, v.z); m.w = fmaxf(m.w, v.w);
    }
    out[b * (F3 / 4) + f4] = m;
}

// ---------------- host orchestration ----------------
static void run_gemm64(const float* A, const float* B, const float* Cin, const float* bias,
                       float* C, int M, int Nc, int K,
                       long long sA, long long sB, long long sCin, long long sC,
                       float alpha, float beta, int relu, int batch) {
    dim3 grid((Nc + 63) / 64, (M + 63) / 64, batch);
    gemm_kernel<<<grid, dim3(16, 16)>>>(A, B, Cin, bias, C, M, Nc, K,
                                        sA, sB, sCin, sC, alpha, beta, relu);
}

static void run_tgemm(const float* A, const float* B, const float* Cin, const float* Cin2,
                      const float* bias, const float* sqv, const float* rs, const float* dvec,
                      float* C, int Nc, int K,
                      long long sA, long long sB, long long sCin, long long sCin2, long long sC,
                      float alpha, float beta, float beta2, int relu, int expmode, int transB) {
    dim3 grid((Nc + TBN - 1) / TBN, NN / TBM, BB);
    tgemm_kernel<<<grid, 256>>>(A, B, Cin, Cin2, bias, sqv, rs, dvec, C, Nc, K,
                                sA, sB, sCin, sCin2, sC,
                                alpha, beta, beta2, relu, expmode, transB);
}

static void run_layer(const float* xin, int Fin, int Fout,
                      const float* W, const float* bias, float* xout,
                      float* Aadj, float* sq, float* dis, float* t1, float* t2) {
    long long sNF = (long long)NN * Fin;
    long long sLL = (long long)NN * NN;
    long long sNO = (long long)NN * Fout;
    bool tc = (Fin % 16) == 0;

    rowsq_kernel<<<BB * NN / 8, 256>>>(xin, sq, Fin);
    if (tc) {
        run_tgemm(xin, xin, nullptr, nullptr, nullptr, sq, nullptr, nullptr,
                  Aadj, NN, Fin, sNF, sNF, 0, 0, sLL,
                  1.f, 0.f, 0.f, 0, 1, 1);
    } else {
        gram_exp_kernel<<<dim3(NN / 64, NN / 64, BB), dim3(16, 16)>>>(xin, sq, Aadj, Fin);
    }
    deg_kernel<<<BB * NN / 8, 256>>>(Aadj, dis);
    // normalization folded into the GEMMs: L@v = v - dn .* (A @ (dm .* v))

    // t1 = L @ xin = xin - dn.*(A@(dm.*xin))
    run_tgemm(Aadj, xin, xin, nullptr, nullptr, nullptr, dis, dis,
              t1, Fin, NN, sLL, sNF, sNF, 0, sNF,
              -1.f, 1.f, 0.f, 0, 0, 0);
    // t2 = 2 L@t1 - xin = 2*t1 - 2*dn.*(A@(dm.*t1)) - xin
    run_tgemm(Aadj, t1, t1, xin, nullptr, nullptr, dis, dis,
              t2, Fin, NN, sLL, sNF, sNF, sNF, sNF,
              -2.f, 2.f, -1.f, 0, 0, 0);

    if (tc) {
        run_tgemm(xin, W, nullptr, nullptr, nullptr, nullptr, nullptr, nullptr,
                  xout, Fout, Fin, sNF, 0, 0, 0, sNO,
                  1.f, 0.f, 0.f, 0, 0, 0);
        run_tgemm(t1, W + (size_t)Fin * Fout, xout, nullptr, nullptr, nullptr, nullptr, nullptr,
                  xout, Fout, Fin, sNF, 0, sNO, 0, sNO,
                  1.f, 1.f, 0.f, 0, 0, 0);
        run_tgemm(t2, W + 2 * (size_t)Fin * Fout, xout, nullptr, bias, nullptr, nullptr, nullptr,
                  xout, Fout, Fin, sNF, 0, sNO, 0, sNO,
                  1.f, 1.f, 0.f, 1, 0, 0);
    } else {
        run_gemm64(xin, W, nullptr, nullptr, xout, NN, Fout, Fin,
                   sNF, 0, 0, sNO, 1.f, 0.f, 0, BB);
        run_gemm64(t1, W + (size_t)Fin * Fout, xout, nullptr, xout, NN, Fout, Fin,
                   sNF, 0, sNO, sNO, 1.f, 1.f, 0, BB);
        run_gemm64(t2, W + 2 * (size_t)Fin * Fout, xout, bias, xout, NN, Fout, Fin,
                   sNF, 0, sNO, sNO, 1.f, 1.f, 1, BB);
    }
}

extern "C" void kernel_launch(void* const* d_in, const int* in_sizes, int n_in,
                              void* d_out, int out_size) {
    const float* x     = (const float*)d_in[0];
    const float* W1    = (const float*)d_in[1];
    const float* b1    = (const float*)d_in[2];
    const float* W2    = (const float*)d_in[3];
    const float* b2    = (const float*)d_in[4];
    const float* W3    = (const float*)d_in[5];
    const float* b3    = (const float*)d_in[6];
    const float* fc1_w = (const float*)d_in[7];
    const float* fc1_b = (const float*)d_in[8];
    const float* fc2_w = (const float*)d_in[9];
    const float* fc2_b = (const float*)d_in[10];
    const float* fc3_w = (const float*)d_in[11];
    const float* fc3_b = (const float*)d_in[12];

    float *Aadj, *feat, *mid, *t1, *t2, *sq, *dis, *pool, *fc1b, *fc2b;
    cudaGetSymbolAddress((void**)&Aadj, g_A);
    cudaGetSymbolAddress((void**)&feat, g_feat);
    cudaGetSymbolAddress((void**)&mid,  g_mid);
    cudaGetSymbolAddress((void**)&t1,   g_t1);
    cudaGetSymbolAddress((void**)&t2,   g_t2);
    cudaGetSymbolAddress((void**)&sq,   g_sq);
    cudaGetSymbolAddress((void**)&dis,  g_dis);
    cudaGetSymbolAddress((void**)&pool, g_pool);
    cudaGetSymbolAddress((void**)&fc1b, g_fc1);
    cudaGetSymbolAddress((void**)&fc2b, g_fc2);

    // three Chebyshev graph-conv layers
    run_layer(x,    FIN, F1, W1, b1, feat, Aadj, sq, dis, t1, t2);   // [B,N,128]
    run_layer(feat, F1,  F2, W2, b2, mid,  Aadj, sq, dis, t1, t2);   // [B,N,512]
    run_layer(mid,  F2,  F3, W3, b3, feat, Aadj, sq, dis, t1, t2);   // [B,N,1024]

    // global max pool
    maxpool_kernel<<<dim3((F3 / 4 + 255) / 256, BB), 256>>>((const float4*)feat, (float4*)pool);

    // FC head (tiny — SIMT)
    run_gemm64(pool, fc1_w, nullptr, fc1_b, fc1b, BB, 512, 1024, 0, 0, 0, 0, 1.f, 0.f, 1, 1);
    run_gemm64(fc1b, fc2_w, nullptr, fc2_b, fc2b, BB, 128, 512,  0, 0, 0, 0, 1.f, 0.f, 1, 1);
    run_gemm64(fc2b, fc3_w, nullptr, fc3_b, (float*)d_out, BB, CLS, 128,
               0, 0, 0, 0, 1.f, 0.f, 0, 1);
}